// round 8
// baseline (speedup 1.0000x reference)
#include <cuda_runtime.h>
#include <math.h>

// Problem constants
#define BB   4
#define TT   2048
#define DD   512
#define HH   8
#define DHD  64
#define MR   (BB*TT)       // 8192
#define QKVN (3*DD)        // 1536

// Scratch (device globals -- allocation-free)
__device__ float g_qkv[MR * QKVN];
__device__ float g_q[BB*HH*TT*DHD];       // [b,h,t,d] (tf32-rounded)
__device__ float g_k[BB*HH*TT*DHD];
__device__ float g_v[BB*HH*TT*DHD];
__device__ float g_att[MR * DD];          // [b*t][D] (tf32-rounded)
__device__ float g_xr[MR * DD];           // x, tf32-rounded
__device__ float g_wqkvr[QKVN * DD];      // w_qkv, tf32-rounded
__device__ float g_wprojr[DD * DD];       // w_proj, tf32-rounded

// ---------------------------------------------------------------------------
// helpers
// ---------------------------------------------------------------------------
__device__ __forceinline__ float tf32r(float x)
{
    unsigned u;
    asm("cvt.rna.tf32.f32 %0, %1;" : "=r"(u) : "f"(x));
    return __uint_as_float(u);
}

__device__ __forceinline__ void mma_tf32(float c[4],
                                         unsigned a0, unsigned a1,
                                         unsigned a2, unsigned a3,
                                         unsigned b0, unsigned b1)
{
    asm volatile(
        "mma.sync.aligned.m16n8k8.row.col.f32.tf32.tf32.f32 "
        "{%0,%1,%2,%3}, {%4,%5,%6,%7}, {%8,%9}, {%0,%1,%2,%3};"
        : "+f"(c[0]), "+f"(c[1]), "+f"(c[2]), "+f"(c[3])
        : "r"(a0), "r"(a1), "r"(a2), "r"(a3), "r"(b0), "r"(b1));
}

__device__ __forceinline__ void cp_async16(unsigned dst, const void* src)
{
    asm volatile("cp.async.cg.shared.global [%0], [%1], 16;\n"
                 :: "r"(dst), "l"(src));
}
__device__ __forceinline__ void cp_commit()
{
    asm volatile("cp.async.commit_group;\n");
}
template<int N> __device__ __forceinline__ void cp_wait()
{
    asm volatile("cp.async.wait_group %0;\n" :: "n"(N));
}

// ---------------------------------------------------------------------------
// pre-round to tf32
// ---------------------------------------------------------------------------
__global__ void round_tf32_kernel(const float4* __restrict__ src,
                                  float4* __restrict__ dst, int n4)
{
    int i = blockIdx.x * blockDim.x + threadIdx.x;
    if (i < n4) {
        float4 v = src[i];
        v.x = tf32r(v.x); v.y = tf32r(v.y);
        v.z = tf32r(v.z); v.w = tf32r(v.w);
        dst[i] = v;
    }
}

// ---------------------------------------------------------------------------
// tf32 GEMM, 3-stage cp.async: C = A[M,K] @ Bw[N,K]^T + bias
// Inputs already tf32-rounded. 128x128x32, 8 warps, warp = 32m x 64n.
// ---------------------------------------------------------------------------
#define TBM 128
#define TBN 128
#define TBK 32
#define TS  36
#define NSTG 3
#define GEMM_SMEM (NSTG * 2 * TBM * TS * 4)

__global__ __launch_bounds__(256, 2)
void gemm_tf32_db_kernel(const float* __restrict__ A,
                         const float* __restrict__ Bw,
                         const float* __restrict__ bias,
                         float* __restrict__ C,
                         int N, int K)
{
    extern __shared__ float gsm[];
    float* As = gsm;                          // [NSTG][TBM*TS]
    float* Bs = gsm + NSTG * TBM * TS;        // [NSTG][TBN*TS]

    const int tid  = threadIdx.x;
    const int warp = tid >> 5;
    const int lane = tid & 31;
    const int gid  = lane >> 2;
    const int tig  = lane & 3;
    const int mw   = warp >> 1;
    const int nw   = warp & 1;

    const int mBase = blockIdx.y * TBM;
    const int nBase = blockIdx.x * TBN;

    const unsigned asb = (unsigned)__cvta_generic_to_shared(As);
    const unsigned bsb = (unsigned)__cvta_generic_to_shared(Bs);

    float acc[2][8][4];
#pragma unroll
    for (int mi = 0; mi < 2; mi++)
#pragma unroll
        for (int j = 0; j < 8; j++)
#pragma unroll
            for (int i = 0; i < 4; i++) acc[mi][j][i] = 0.0f;

    const int niter = K / TBK;

    const int crow = tid >> 3;
    const int cc4  = (tid & 7) << 2;

    auto issue = [&](int kt, int buf) {
        const int k0 = kt * TBK;
        const unsigned abuf = asb + (unsigned)(buf * TBM * TS) * 4u;
        const unsigned bbuf = bsb + (unsigned)(buf * TBN * TS) * 4u;
#pragma unroll
        for (int l = 0; l < 4; l++) {
            int row = crow + l * 32;
            cp_async16(abuf + (unsigned)(row * TS + cc4) * 4u,
                       &A[(size_t)(mBase + row) * K + k0 + cc4]);
        }
#pragma unroll
        for (int l = 0; l < 4; l++) {
            int row = crow + l * 32;
            cp_async16(bbuf + (unsigned)(row * TS + cc4) * 4u,
                       &Bw[(size_t)(nBase + row) * K + k0 + cc4]);
        }
        cp_commit();
    };

    issue(0, 0);
    issue(1, 1);

    for (int i = 0; i < niter; i++) {
        if (i + 1 < niter) cp_wait<1>();
        else               cp_wait<0>();
        __syncthreads();
        if (i + 2 < niter) issue(i + 2, (i + 2) % NSTG);

        const int buf = i % NSTG;
        const float* Ab = As + buf * TBM * TS;
        const float* Bb = Bs + buf * TBN * TS;

#pragma unroll
        for (int kk = 0; kk < TBK; kk += 8) {
            unsigned a[2][4];
#pragma unroll
            for (int mi = 0; mi < 2; mi++) {
                int r0 = (mw * 32 + mi * 16 + gid) * TS;
                a[mi][0] = __float_as_uint(Ab[r0 + kk + tig]);
                a[mi][1] = __float_as_uint(Ab[r0 + 8 * TS + kk + tig]);
                a[mi][2] = __float_as_uint(Ab[r0 + kk + tig + 4]);
                a[mi][3] = __float_as_uint(Ab[r0 + 8 * TS + kk + tig + 4]);
            }
#pragma unroll
            for (int j = 0; j < 8; j++) {
                int rb = (nw * 64 + j * 8 + gid) * TS;
                unsigned b0 = __float_as_uint(Bb[rb + kk + tig]);
                unsigned b1 = __float_as_uint(Bb[rb + kk + tig + 4]);
                mma_tf32(acc[0][j], a[0][0], a[0][1], a[0][2], a[0][3], b0, b1);
                mma_tf32(acc[1][j], a[1][0], a[1][1], a[1][2], a[1][3], b0, b1);
            }
        }
        __syncthreads();
    }

    // Epilogue: bias + store
#pragma unroll
    for (int mi = 0; mi < 2; mi++) {
        int m0 = mBase + mw * 32 + mi * 16 + gid;
#pragma unroll
        for (int j = 0; j < 8; j++) {
            int col = nBase + nw * 64 + j * 8 + 2 * tig;
            float2 bv = *(const float2*)&bias[col];
            *(float2*)&C[(size_t)m0 * N + col] =
                make_float2(acc[mi][j][0] + bv.x, acc[mi][j][1] + bv.y);
            *(float2*)&C[(size_t)(m0 + 8) * N + col] =
                make_float2(acc[mi][j][2] + bv.x, acc[mi][j][3] + bv.y);
        }
    }
}

// ---------------------------------------------------------------------------
// RoPE + scatter; outputs tf32-rounded
// ---------------------------------------------------------------------------
__global__ void rope_scatter_kernel()
{
    int idx = blockIdx.x * blockDim.x + threadIdx.x;
    if (idx >= BB * TT * HH * 32) return;
    const int j  = idx & 31;
    const int h  = (idx >> 5) & 7;
    const int bt = idx >> 8;
    const int b  = bt / TT;
    const int t  = bt - b * TT;

    const float* row = g_qkv + (size_t)bt * QKVN;
    const int base = h * DHD;

    float inv = exp2f(-(float)j * 0.41524103736593f);  // log2(10000)/32
    float ang = (float)t * inv;
    float s, c;
    sincosf(ang, &s, &c);

    float q1 = row[base + j],        q2 = row[base + j + 32];
    float k1 = row[DD + base + j],   k2 = row[DD + base + j + 32];
    float v1 = row[2*DD + base + j], v2 = row[2*DD + base + j + 32];

    size_t o = ((size_t)(b * HH + h) * TT + t) * DHD;
    g_q[o + j]      = tf32r(q1 * c - q2 * s);
    g_q[o + j + 32] = tf32r(q2 * c + q1 * s);
    g_k[o + j]      = tf32r(k1 * c - k2 * s);
    g_k[o + j + 32] = tf32r(k2 * c + k1 * s);
    g_v[o + j]      = tf32r(v1);
    g_v[o + j + 32] = tf32r(v2);
}

// ---------------------------------------------------------------------------
// Flash attention v5: tf32 mma, cp.async double-buffered K/V, mask prefetch.
// ---------------------------------------------------------------------------
#define QTILE 128
#define KTILE 64
#define SQ 68
#define SV 72
#define KBUF (KTILE * SQ)       // 4352 floats
#define VBUF (KTILE * SV)       // 4608 floats
#define ATT_SMEM ((QTILE*SQ + 2*KBUF + 2*VBUF) * 4)   // 106496 B

__device__ __forceinline__ float shfl4(float v, int src)
{
    return __shfl_sync(0xffffffffu, v, src, 4);
}

__global__ __launch_bounds__(256, 2)
void attn_kernel(const float* __restrict__ mask)
{
    extern __shared__ float smf[];
    float* Qs = smf;                       // [128][SQ]
    float* Ks = Qs + QTILE * SQ;           // [2][64][SQ]
    float* Vs = Ks + 2 * KBUF;             // [2][64][SV]

    const int bh   = blockIdx.y;
    const int b    = bh >> 3;
    const int h    = bh & 7;
    const int q0   = blockIdx.x * QTILE;
    const int tid  = threadIdx.x;
    const int warp = tid >> 5;
    const int lane = tid & 31;
    const int gid  = lane >> 2;
    const int tig  = lane & 3;
    const int qrow = warp * 16;

    const float scale = 0.125f;

    const unsigned ks_u = (unsigned)__cvta_generic_to_shared(Ks);
    const unsigned vs_u = (unsigned)__cvta_generic_to_shared(Vs);

    const float* kbase = g_k + (size_t)bh * TT * DHD;
    const float* vbase = g_v + (size_t)bh * TT * DHD;

    // per-thread staging coords (4 float4 each for K and V)
    const int srow = tid >> 2;             // 0..63
    const int sc4  = (tid & 3) << 2;       // 0,4,8,12 (of 16 per row -> x4)

    auto issue = [&](int kt, int buf) {
        const int k0 = kt * KTILE;
        const unsigned kb = ks_u + (unsigned)(buf * KBUF) * 4u;
        const unsigned vb = vs_u + (unsigned)(buf * VBUF) * 4u;
        const float* kptr = kbase + (size_t)k0 * DHD;
        const float* vptr = vbase + (size_t)k0 * DHD;
#pragma unroll
        for (int l = 0; l < 4; l++) {
            int c4 = sc4 + l * 16;
            cp_async16(kb + (unsigned)(srow * SQ + c4) * 4u,
                       &kptr[srow * DHD + c4]);
            cp_async16(vb + (unsigned)(srow * SV + c4) * 4u,
                       &vptr[srow * DHD + c4]);
        }
        cp_commit();
    };

    // Stage Q (plain; once)
    const float* qptr = g_q + ((size_t)bh * TT + q0) * DHD;
    for (int l = tid; l < QTILE * 16; l += 256) {
        int r  = l >> 4;
        int c4 = (l & 15) << 2;
        *(float4*)&Qs[r * SQ + c4] = *(const float4*)&qptr[r * DHD + c4];
    }

    issue(0, 0);

    float o[8][4];
#pragma unroll
    for (int j = 0; j < 8; j++)
#pragma unroll
        for (int i = 0; i < 4; i++) o[j][i] = 0.0f;
    float m0 = -1e30f, m1 = -1e30f, l0 = 0.0f, l1 = 0.0f;

    const float* mrow0base = mask + ((size_t)b * TT + q0 + qrow + gid) * TT;

    const int ntiles = TT / KTILE;
    for (int kt = 0; kt < ntiles; kt++) {
        const int k0 = kt * KTILE;

        __syncthreads();   // all warps done with buffer (kt+1)&1 from tile kt-1
        if (kt + 1 < ntiles) { issue(kt + 1, (kt + 1) & 1); cp_wait<1>(); }
        else                 { cp_wait<0>(); }
        __syncthreads();   // tile kt staged & visible

        const float* Kb = Ks + (kt & 1) * KBUF;
        const float* Vb = Vs + (kt & 1) * VBUF;

        // ---- prefetch mask tile into registers (hidden behind QK mmas) ----
        float2 pm0[8], pm1[8];
        {
            const float* mr0 = mrow0base + k0;
            const float* mr1 = mr0 + 8 * TT;
#pragma unroll
            for (int j = 0; j < 8; j++) {
                pm0[j] = *(const float2*)&mr0[j * 8 + 2 * tig];
                pm1[j] = *(const float2*)&mr1[j * 8 + 2 * tig];
            }
        }

        // ---- S = Q K^T ----
        float c[8][4];
#pragma unroll
        for (int j = 0; j < 8; j++)
#pragma unroll
            for (int i = 0; i < 4; i++) c[j][i] = 0.0f;

#pragma unroll
        for (int d0 = 0; d0 < 64; d0 += 8) {
            unsigned a0 = __float_as_uint(Qs[(qrow + gid) * SQ + d0 + tig]);
            unsigned a1 = __float_as_uint(Qs[(qrow + gid + 8) * SQ + d0 + tig]);
            unsigned a2 = __float_as_uint(Qs[(qrow + gid) * SQ + d0 + tig + 4]);
            unsigned a3 = __float_as_uint(Qs[(qrow + gid + 8) * SQ + d0 + tig + 4]);
#pragma unroll
            for (int j = 0; j < 8; j++) {
                unsigned b0 = __float_as_uint(Kb[(j * 8 + gid) * SQ + d0 + tig]);
                unsigned b1 = __float_as_uint(Kb[(j * 8 + gid) * SQ + d0 + tig + 4]);
                mma_tf32(c[j], a0, a1, a2, a3, b0, b1);
            }
        }

        // ---- scale + mask (prefetched) ----
#pragma unroll
        for (int j = 0; j < 8; j++) {
            c[j][0] = fmaf(c[j][0], scale, pm0[j].x);
            c[j][1] = fmaf(c[j][1], scale, pm0[j].y);
            c[j][2] = fmaf(c[j][2], scale, pm1[j].x);
            c[j][3] = fmaf(c[j][3], scale, pm1[j].y);
        }

        // ---- online softmax (quad reduction) ----
        float mt0 = -1e30f, mt1 = -1e30f;
#pragma unroll
        for (int j = 0; j < 8; j++) {
            mt0 = fmaxf(mt0, fmaxf(c[j][0], c[j][1]));
            mt1 = fmaxf(mt1, fmaxf(c[j][2], c[j][3]));
        }
        mt0 = fmaxf(mt0, __shfl_xor_sync(0xffffffffu, mt0, 1));
        mt0 = fmaxf(mt0, __shfl_xor_sync(0xffffffffu, mt0, 2));
        mt1 = fmaxf(mt1, __shfl_xor_sync(0xffffffffu, mt1, 1));
        mt1 = fmaxf(mt1, __shfl_xor_sync(0xffffffffu, mt1, 2));

        float mn0 = fmaxf(m0, mt0);
        float mn1 = fmaxf(m1, mt1);
        float cor0 = __expf(m0 - mn0);
        float cor1 = __expf(m1 - mn1);
        m0 = mn0; m1 = mn1;

        float rs0 = 0.0f, rs1 = 0.0f;
#pragma unroll
        for (int j = 0; j < 8; j++) {
            c[j][0] = __expf(c[j][0] - mn0);
            c[j][1] = __expf(c[j][1] - mn0);
            c[j][2] = __expf(c[j][2] - mn1);
            c[j][3] = __expf(c[j][3] - mn1);
            rs0 += c[j][0] + c[j][1];
            rs1 += c[j][2] + c[j][3];
        }
        rs0 += __shfl_xor_sync(0xffffffffu, rs0, 1);
        rs0 += __shfl_xor_sync(0xffffffffu, rs0, 2);
        rs1 += __shfl_xor_sync(0xffffffffu, rs1, 1);
        rs1 += __shfl_xor_sync(0xffffffffu, rs1, 2);
        l0 = l0 * cor0 + rs0;
        l1 = l1 * cor1 + rs1;

#pragma unroll
        for (int j = 0; j < 8; j++) {
            o[j][0] *= cor0; o[j][1] *= cor0;
            o[j][2] *= cor1; o[j][3] *= cor1;
        }

        // ---- round P; O += P V with C->A frag via quad shuffles ----
#pragma unroll
        for (int j = 0; j < 8; j++) {
            c[j][0] = tf32r(c[j][0]); c[j][1] = tf32r(c[j][1]);
            c[j][2] = tf32r(c[j][2]); c[j][3] = tf32r(c[j][3]);
        }

        const int s0  = tig >> 1;
        const int sel = tig & 1;
#pragma unroll
        for (int mblk = 0; mblk < 8; mblk++) {
            float x00 = shfl4(c[mblk][0], s0);
            float x01 = shfl4(c[mblk][1], s0);
            float x20 = shfl4(c[mblk][2], s0);
            float x21 = shfl4(c[mblk][3], s0);
            float y00 = shfl4(c[mblk][0], s0 + 2);
            float y01 = shfl4(c[mblk][1], s0 + 2);
            float y20 = shfl4(c[mblk][2], s0 + 2);
            float y21 = shfl4(c[mblk][3], s0 + 2);
            unsigned a0 = __float_as_uint(sel ? x01 : x00);
            unsigned a1 = __float_as_uint(sel ? x21 : x20);
            unsigned a2 = __float_as_uint(sel ? y01 : y00);
            unsigned a3 = __float_as_uint(sel ? y21 : y20);
#pragma unroll
            for (int j = 0; j < 8; j++) {
                unsigned b0 = __float_as_uint(Vb[(mblk * 8 + tig) * SV + j * 8 + gid]);
                unsigned b1 = __float_as_uint(Vb[(mblk * 8 + tig + 4) * SV + j * 8 + gid]);
                mma_tf32(o[j], a0, a1, a2, a3, b0, b1);
            }
        }
    }

    // ---- normalize + write g_att (tf32-rounded for proj GEMM) ----
    float il0 = 1.0f / l0;
    float il1 = 1.0f / l1;
    size_t r0 = (size_t)b * TT + q0 + qrow + gid;
    float* ap0 = g_att + r0 * DD + h * DHD;
    float* ap1 = ap0 + (size_t)8 * DD;
#pragma unroll
    for (int j = 0; j < 8; j++) {
        *(float2*)&ap0[j * 8 + 2 * tig] =
            make_float2(tf32r(o[j][0] * il0), tf32r(o[j][1] * il0));
        *(float2*)&ap1[j * 8 + 2 * tig] =
            make_float2(tf32r(o[j][2] * il1), tf32r(o[j][3] * il1));
    }
}

// ---------------------------------------------------------------------------
// Launch
// ---------------------------------------------------------------------------
extern "C" void kernel_launch(void* const* d_in, const int* in_sizes, int n_in,
                              void* d_out, int out_size)
{
    const float* x      = (const float*)d_in[0];
    const float* mask   = (const float*)d_in[1];
    const float* w_qkv  = (const float*)d_in[2];
    const float* b_qkv  = (const float*)d_in[3];
    const float* w_proj = (const float*)d_in[4];
    const float* b_proj = (const float*)d_in[5];
    float* out = (float*)d_out;

    float* qkv;   cudaGetSymbolAddress((void**)&qkv,   g_qkv);
    float* att;   cudaGetSymbolAddress((void**)&att,   g_att);
    float* xr;    cudaGetSymbolAddress((void**)&xr,    g_xr);
    float* wqr;   cudaGetSymbolAddress((void**)&wqr,   g_wqkvr);
    float* wpr;   cudaGetSymbolAddress((void**)&wpr,   g_wprojr);

    cudaFuncSetAttribute(gemm_tf32_db_kernel,
                         cudaFuncAttributeMaxDynamicSharedMemorySize, GEMM_SMEM);
    cudaFuncSetAttribute(attn_kernel,
                         cudaFuncAttributeMaxDynamicSharedMemorySize, ATT_SMEM);

    // 0) pre-round inputs to tf32
    {
        int n4 = MR * DD / 4;
        round_tf32_kernel<<<(n4 + 255) / 256, 256>>>((const float4*)x, (float4*)xr, n4);
        n4 = QKVN * DD / 4;
        round_tf32_kernel<<<(n4 + 255) / 256, 256>>>((const float4*)w_qkv, (float4*)wqr, n4);
        n4 = DD * DD / 4;
        round_tf32_kernel<<<(n4 + 255) / 256, 256>>>((const float4*)w_proj, (float4*)wpr, n4);
    }

    // 1) QKV projection
    {
        dim3 grid(QKVN / TBN, MR / TBM);
        gemm_tf32_db_kernel<<<grid, 256, GEMM_SMEM>>>(xr, wqr, b_qkv, qkv, QKVN, DD);
    }

    // 2) RoPE + scatter
    {
        int total = BB * TT * HH * 32;
        rope_scatter_kernel<<<(total + 255) / 256, 256>>>();
    }

    // 3) Flash attention
    {
        dim3 grid(TT / QTILE, BB * HH);
        attn_kernel<<<grid, 256, ATT_SMEM>>>(mask);
    }

    // 4) Output projection
    {
        dim3 grid(DD / TBN, MR / TBM);
        gemm_tf32_db_kernel<<<grid, 256, GEMM_SMEM>>>(att, wpr, b_proj, out, DD, DD);
    }
}

// round 11
// speedup vs baseline: 1.0509x; 1.0509x over previous
#include <cuda_runtime.h>
#include <math.h>
#include <stdint.h>

// Problem constants
#define BB   4
#define TT   2048
#define DD   512
#define HH   8
#define DHD  64
#define MR   (BB*TT)       // 8192
#define QKVN (3*DD)        // 1536

// Scratch (device globals -- allocation-free)
__device__ float g_qkv[MR * QKVN];
__device__ float g_q[BB*HH*TT*DHD];       // [b,h,t,d] tf32-rounded
__device__ float g_k[BB*HH*TT*DHD];
__device__ float g_v[BB*HH*TT*DHD];
__device__ float g_att[MR * DD];          // [b*t][D] tf32-rounded
__device__ float g_xr[MR * DD];
__device__ float g_wqkvr[QKVN * DD];
__device__ float g_wprojr[DD * DD];
__device__ int   g_mask_nz;               // 1 if mask has any nonzero

// ---------------------------------------------------------------------------
// helpers
// ---------------------------------------------------------------------------
__device__ __forceinline__ float tf32r(float x)
{
    unsigned u;
    asm("cvt.rna.tf32.f32 %0, %1;" : "=r"(u) : "f"(x));
    return __uint_as_float(u);
}

__device__ __forceinline__ void mma_tf32(float c[4],
                                         unsigned a0, unsigned a1,
                                         unsigned a2, unsigned a3,
                                         unsigned b0, unsigned b1)
{
    asm volatile(
        "mma.sync.aligned.m16n8k8.row.col.f32.tf32.tf32.f32 "
        "{%0,%1,%2,%3}, {%4,%5,%6,%7}, {%8,%9}, {%0,%1,%2,%3};"
        : "+f"(c[0]), "+f"(c[1]), "+f"(c[2]), "+f"(c[3])
        : "r"(a0), "r"(a1), "r"(a2), "r"(a3), "r"(b0), "r"(b1));
}

__device__ __forceinline__ void cp_async16(unsigned dst, const void* src)
{
    asm volatile("cp.async.cg.shared.global [%0], [%1], 16;\n"
                 :: "r"(dst), "l"(src));
}
__device__ __forceinline__ void cp_commit()
{
    asm volatile("cp.async.commit_group;\n");
}
template<int N> __device__ __forceinline__ void cp_wait()
{
    asm volatile("cp.async.wait_group %0;\n" :: "n"(N));
}

__device__ __forceinline__ unsigned smem_u32(const void* p)
{
    return (unsigned)__cvta_generic_to_shared(p);
}

// ---------------------------------------------------------------------------
// pre-round to tf32
// ---------------------------------------------------------------------------
__global__ void round_tf32_kernel(const float4* __restrict__ src,
                                  float4* __restrict__ dst, int n4)
{
    int i = blockIdx.x * blockDim.x + threadIdx.x;
    if (i < n4) {
        float4 v = src[i];
        v.x = tf32r(v.x); v.y = tf32r(v.y);
        v.z = tf32r(v.z); v.w = tf32r(v.w);
        dst[i] = v;
    }
}

// ---------------------------------------------------------------------------
// mask zero-check: g_mask_nz = (any mask element != 0)
// ---------------------------------------------------------------------------
__global__ void mask_reset_kernel() { g_mask_nz = 0; }

__global__ void mask_check_kernel(const float4* __restrict__ m, int n4)
{
    if (g_mask_nz) return;   // someone already found nonzero
    int stride = gridDim.x * blockDim.x;
    int found = 0;
    for (int i = blockIdx.x * blockDim.x + threadIdx.x; i < n4; i += stride) {
        float4 v = m[i];
        if (v.x != 0.0f || v.y != 0.0f || v.z != 0.0f || v.w != 0.0f) {
            found = 1;
            break;
        }
    }
    if (__syncthreads_or(found)) {
        if (threadIdx.x == 0) atomicExch(&g_mask_nz, 1);
    }
}

// ---------------------------------------------------------------------------
// tf32 GEMM, 3-stage cp.async: C = A[M,K] @ Bw[N,K]^T + bias  (R8 version)
// ---------------------------------------------------------------------------
#define TBM 128
#define TBN 128
#define TBK 32
#define TS  36
#define NSTG 3
#define GEMM_SMEM (NSTG * 2 * TBM * TS * 4)

__global__ __launch_bounds__(256, 2)
void gemm_tf32_db_kernel(const float* __restrict__ A,
                         const float* __restrict__ Bw,
                         const float* __restrict__ bias,
                         float* __restrict__ C,
                         int N, int K)
{
    extern __shared__ float gsm[];
    float* As = gsm;
    float* Bs = gsm + NSTG * TBM * TS;

    const int tid  = threadIdx.x;
    const int warp = tid >> 5;
    const int lane = tid & 31;
    const int gid  = lane >> 2;
    const int tig  = lane & 3;
    const int mw   = warp >> 1;
    const int nw   = warp & 1;

    const int mBase = blockIdx.y * TBM;
    const int nBase = blockIdx.x * TBN;

    const unsigned asb = smem_u32(As);
    const unsigned bsb = smem_u32(Bs);

    float acc[2][8][4];
#pragma unroll
    for (int mi = 0; mi < 2; mi++)
#pragma unroll
        for (int j = 0; j < 8; j++)
#pragma unroll
            for (int i = 0; i < 4; i++) acc[mi][j][i] = 0.0f;

    const int niter = K / TBK;
    const int crow = tid >> 3;
    const int cc4  = (tid & 7) << 2;

    auto issue = [&](int kt, int buf) {
        const int k0 = kt * TBK;
        const unsigned abuf = asb + (unsigned)(buf * TBM * TS) * 4u;
        const unsigned bbuf = bsb + (unsigned)(buf * TBN * TS) * 4u;
#pragma unroll
        for (int l = 0; l < 4; l++) {
            int row = crow + l * 32;
            cp_async16(abuf + (unsigned)(row * TS + cc4) * 4u,
                       &A[(size_t)(mBase + row) * K + k0 + cc4]);
        }
#pragma unroll
        for (int l = 0; l < 4; l++) {
            int row = crow + l * 32;
            cp_async16(bbuf + (unsigned)(row * TS + cc4) * 4u,
                       &Bw[(size_t)(nBase + row) * K + k0 + cc4]);
        }
        cp_commit();
    };

    issue(0, 0);
    issue(1, 1);

    for (int i = 0; i < niter; i++) {
        if (i + 1 < niter) cp_wait<1>();
        else               cp_wait<0>();
        __syncthreads();
        if (i + 2 < niter) issue(i + 2, (i + 2) % NSTG);

        const int buf = i % NSTG;
        const float* Ab = As + buf * TBM * TS;
        const float* Bb = Bs + buf * TBN * TS;

#pragma unroll
        for (int kk = 0; kk < TBK; kk += 8) {
            unsigned a[2][4];
#pragma unroll
            for (int mi = 0; mi < 2; mi++) {
                int r0 = (mw * 32 + mi * 16 + gid) * TS;
                a[mi][0] = __float_as_uint(Ab[r0 + kk + tig]);
                a[mi][1] = __float_as_uint(Ab[r0 + 8 * TS + kk + tig]);
                a[mi][2] = __float_as_uint(Ab[r0 + kk + tig + 4]);
                a[mi][3] = __float_as_uint(Ab[r0 + 8 * TS + kk + tig + 4]);
            }
#pragma unroll
            for (int j = 0; j < 8; j++) {
                int rb = (nw * 64 + j * 8 + gid) * TS;
                unsigned b0 = __float_as_uint(Bb[rb + kk + tig]);
                unsigned b1 = __float_as_uint(Bb[rb + kk + tig + 4]);
                mma_tf32(acc[0][j], a[0][0], a[0][1], a[0][2], a[0][3], b0, b1);
                mma_tf32(acc[1][j], a[1][0], a[1][1], a[1][2], a[1][3], b0, b1);
            }
        }
        __syncthreads();
    }

#pragma unroll
    for (int mi = 0; mi < 2; mi++) {
        int m0 = mBase + mw * 32 + mi * 16 + gid;
#pragma unroll
        for (int j = 0; j < 8; j++) {
            int col = nBase + nw * 64 + j * 8 + 2 * tig;
            float2 bv = *(const float2*)&bias[col];
            *(float2*)&C[(size_t)m0 * N + col] =
                make_float2(acc[mi][j][0] + bv.x, acc[mi][j][1] + bv.y);
            *(float2*)&C[(size_t)(m0 + 8) * N + col] =
                make_float2(acc[mi][j][2] + bv.x, acc[mi][j][3] + bv.y);
        }
    }
}

// ---------------------------------------------------------------------------
// RoPE + scatter; outputs tf32-rounded (R8 version)
// ---------------------------------------------------------------------------
__global__ void rope_scatter_kernel()
{
    int idx = blockIdx.x * blockDim.x + threadIdx.x;
    if (idx >= BB * TT * HH * 32) return;
    const int j  = idx & 31;
    const int h  = (idx >> 5) & 7;
    const int bt = idx >> 8;
    const int b  = bt / TT;
    const int t  = bt - b * TT;

    const float* row = g_qkv + (size_t)bt * QKVN;
    const int base = h * DHD;

    float inv = exp2f(-(float)j * 0.41524103736593f);  // log2(10000)/32
    float ang = (float)t * inv;
    float s, c;
    sincosf(ang, &s, &c);

    float q1 = row[base + j],        q2 = row[base + j + 32];
    float k1 = row[DD + base + j],   k2 = row[DD + base + j + 32];
    float v1 = row[2*DD + base + j], v2 = row[2*DD + base + j + 32];

    size_t o = ((size_t)(b * HH + h) * TT + t) * DHD;
    g_q[o + j]      = tf32r(q1 * c - q2 * s);
    g_q[o + j + 32] = tf32r(q2 * c + q1 * s);
    g_k[o + j]      = tf32r(k1 * c - k2 * s);
    g_k[o + j + 32] = tf32r(k2 * c + k1 * s);
    g_v[o + j]      = tf32r(v1);
    g_v[o + j + 32] = tf32r(v2);
}

// ---------------------------------------------------------------------------
// Flash attention v7: R8 tf32 pipeline + zero-mask fast path.
// ---------------------------------------------------------------------------
#define QTILE 128
#define KTILE 64
#define SQ 68
#define SV 72
#define KBUF (KTILE * SQ)
#define VBUF (KTILE * SV)
#define ATT_SMEM ((QTILE*SQ + 2*KBUF + 2*VBUF) * 4)

__device__ __forceinline__ float shfl4(float v, int src)
{
    return __shfl_sync(0xffffffffu, v, src, 4);
}

__global__ __launch_bounds__(256, 2)
void attn_kernel(const float* __restrict__ mask)
{
    extern __shared__ float smf[];
    float* Qs = smf;
    float* Ks = Qs + QTILE * SQ;
    float* Vs = Ks + 2 * KBUF;

    const int bh   = blockIdx.y;
    const int b    = bh >> 3;
    const int h    = bh & 7;
    const int q0   = blockIdx.x * QTILE;
    const int tid  = threadIdx.x;
    const int warp = tid >> 5;
    const int lane = tid & 31;
    const int gid  = lane >> 2;
    const int tig  = lane & 3;
    const int qrow = warp * 16;

    const float scale = 0.125f;
    const bool has_mask = (g_mask_nz != 0);   // uniform branch

    const unsigned ks_u = smem_u32(Ks);
    const unsigned vs_u = smem_u32(Vs);

    const float* kbase = g_k + (size_t)bh * TT * DHD;
    const float* vbase = g_v + (size_t)bh * TT * DHD;

    const int srow = tid >> 2;
    const int sc4  = (tid & 3) << 2;

    auto issue = [&](int kt, int buf) {
        const int k0 = kt * KTILE;
        const unsigned kb = ks_u + (unsigned)(buf * KBUF) * 4u;
        const unsigned vb = vs_u + (unsigned)(buf * VBUF) * 4u;
        const float* kptr = kbase + (size_t)k0 * DHD;
        const float* vptr = vbase + (size_t)k0 * DHD;
#pragma unroll
        for (int l = 0; l < 4; l++) {
            int c4 = sc4 + l * 16;
            cp_async16(kb + (unsigned)(srow * SQ + c4) * 4u,
                       &kptr[srow * DHD + c4]);
            cp_async16(vb + (unsigned)(srow * SV + c4) * 4u,
                       &vptr[srow * DHD + c4]);
        }
        cp_commit();
    };

    const float* qptr = g_q + ((size_t)bh * TT + q0) * DHD;
    for (int l = tid; l < QTILE * 16; l += 256) {
        int r  = l >> 4;
        int c4 = (l & 15) << 2;
        *(float4*)&Qs[r * SQ + c4] = *(const float4*)&qptr[r * DHD + c4];
    }

    issue(0, 0);

    float o[8][4];
#pragma unroll
    for (int j = 0; j < 8; j++)
#pragma unroll
        for (int i = 0; i < 4; i++) o[j][i] = 0.0f;
    float m0 = -1e30f, m1 = -1e30f, l0 = 0.0f, l1 = 0.0f;

    const float* mrow0base = mask + ((size_t)b * TT + q0 + qrow + gid) * TT;

    const int ntiles = TT / KTILE;
    for (int kt = 0; kt < ntiles; kt++) {
        const int k0 = kt * KTILE;

        __syncthreads();
        if (kt + 1 < ntiles) { issue(kt + 1, (kt + 1) & 1); cp_wait<1>(); }
        else                 { cp_wait<0>(); }
        __syncthreads();

        const float* Kb = Ks + (kt & 1) * KBUF;
        const float* Vb = Vs + (kt & 1) * VBUF;

        // mask prefetch only when mask is nonzero
        float2 pm0[8], pm1[8];
        if (has_mask) {
            const float* mr0 = mrow0base + k0;
            const float* mr1 = mr0 + 8 * TT;
#pragma unroll
            for (int j = 0; j < 8; j++) {
                pm0[j] = *(const float2*)&mr0[j * 8 + 2 * tig];
                pm1[j] = *(const float2*)&mr1[j * 8 + 2 * tig];
            }
        }

        // ---- S = Q K^T (tf32) ----
        float c[8][4];
#pragma unroll
        for (int j = 0; j < 8; j++)
#pragma unroll
            for (int i = 0; i < 4; i++) c[j][i] = 0.0f;

#pragma unroll
        for (int d0 = 0; d0 < 64; d0 += 8) {
            unsigned a0 = __float_as_uint(Qs[(qrow + gid) * SQ + d0 + tig]);
            unsigned a1 = __float_as_uint(Qs[(qrow + gid + 8) * SQ + d0 + tig]);
            unsigned a2 = __float_as_uint(Qs[(qrow + gid) * SQ + d0 + tig + 4]);
            unsigned a3 = __float_as_uint(Qs[(qrow + gid + 8) * SQ + d0 + tig + 4]);
#pragma unroll
            for (int j = 0; j < 8; j++) {
                unsigned b0 = __float_as_uint(Kb[(j * 8 + gid) * SQ + d0 + tig]);
                unsigned b1 = __float_as_uint(Kb[(j * 8 + gid) * SQ + d0 + tig + 4]);
                mma_tf32(c[j], a0, a1, a2, a3, b0, b1);
            }
        }

        // ---- scale (+ mask when present) ----
        if (has_mask) {
#pragma unroll
            for (int j = 0; j < 8; j++) {
                c[j][0] = fmaf(c[j][0], scale, pm0[j].x);
                c[j][1] = fmaf(c[j][1], scale, pm0[j].y);
                c[j][2] = fmaf(c[j][2], scale, pm1[j].x);
                c[j][3] = fmaf(c[j][3], scale, pm1[j].y);
            }
        } else {
#pragma unroll
            for (int j = 0; j < 8; j++) {
                c[j][0] *= scale; c[j][1] *= scale;
                c[j][2] *= scale; c[j][3] *= scale;
            }
        }

        // ---- online softmax (quad reduction) ----
        float mt0 = -1e30f, mt1 = -1e30f;
#pragma unroll
        for (int j = 0; j < 8; j++) {
            mt0 = fmaxf(mt0, fmaxf(c[j][0], c[j][1]));
            mt1 = fmaxf(mt1, fmaxf(c[j][2], c[j][3]));
        }
        mt0 = fmaxf(mt0, __shfl_xor_sync(0xffffffffu, mt0, 1));
        mt0 = fmaxf(mt0, __shfl_xor_sync(0xffffffffu, mt0, 2));
        mt1 = fmaxf(mt1, __shfl_xor_sync(0xffffffffu, mt1, 1));
        mt1 = fmaxf(mt1, __shfl_xor_sync(0xffffffffu, mt1, 2));

        float mn0 = fmaxf(m0, mt0);
        float mn1 = fmaxf(m1, mt1);
        float cor0 = __expf(m0 - mn0);
        float cor1 = __expf(m1 - mn1);
        m0 = mn0; m1 = mn1;

        float rs0 = 0.0f, rs1 = 0.0f;
#pragma unroll
        for (int j = 0; j < 8; j++) {
            c[j][0] = __expf(c[j][0] - mn0);
            c[j][1] = __expf(c[j][1] - mn0);
            c[j][2] = __expf(c[j][2] - mn1);
            c[j][3] = __expf(c[j][3] - mn1);
            rs0 += c[j][0] + c[j][1];
            rs1 += c[j][2] + c[j][3];
        }
        rs0 += __shfl_xor_sync(0xffffffffu, rs0, 1);
        rs0 += __shfl_xor_sync(0xffffffffu, rs0, 2);
        rs1 += __shfl_xor_sync(0xffffffffu, rs1, 1);
        rs1 += __shfl_xor_sync(0xffffffffu, rs1, 2);
        l0 = l0 * cor0 + rs0;
        l1 = l1 * cor1 + rs1;

#pragma unroll
        for (int j = 0; j < 8; j++) {
            o[j][0] *= cor0; o[j][1] *= cor0;
            o[j][2] *= cor1; o[j][3] *= cor1;
        }

        // ---- round P; O += P V with C->A frag via quad shuffles ----
#pragma unroll
        for (int j = 0; j < 8; j++) {
            c[j][0] = tf32r(c[j][0]); c[j][1] = tf32r(c[j][1]);
            c[j][2] = tf32r(c[j][2]); c[j][3] = tf32r(c[j][3]);
        }

        const int s0  = tig >> 1;
        const int sel = tig & 1;
#pragma unroll
        for (int mblk = 0; mblk < 8; mblk++) {
            float x00 = shfl4(c[mblk][0], s0);
            float x01 = shfl4(c[mblk][1], s0);
            float x20 = shfl4(c[mblk][2], s0);
            float x21 = shfl4(c[mblk][3], s0);
            float y00 = shfl4(c[mblk][0], s0 + 2);
            float y01 = shfl4(c[mblk][1], s0 + 2);
            float y20 = shfl4(c[mblk][2], s0 + 2);
            float y21 = shfl4(c[mblk][3], s0 + 2);
            unsigned a0 = __float_as_uint(sel ? x01 : x00);
            unsigned a1 = __float_as_uint(sel ? x21 : x20);
            unsigned a2 = __float_as_uint(sel ? y01 : y00);
            unsigned a3 = __float_as_uint(sel ? y21 : y20);
#pragma unroll
            for (int j = 0; j < 8; j++) {
                unsigned b0 = __float_as_uint(Vb[(mblk * 8 + tig) * SV + j * 8 + gid]);
                unsigned b1 = __float_as_uint(Vb[(mblk * 8 + tig + 4) * SV + j * 8 + gid]);
                mma_tf32(o[j], a0, a1, a2, a3, b0, b1);
            }
        }
    }

    float il0 = 1.0f / l0;
    float il1 = 1.0f / l1;
    size_t r0 = (size_t)b * TT + q0 + qrow + gid;
    float* ap0 = g_att + r0 * DD + h * DHD;
    float* ap1 = ap0 + (size_t)8 * DD;
#pragma unroll
    for (int j = 0; j < 8; j++) {
        *(float2*)&ap0[j * 8 + 2 * tig] =
            make_float2(tf32r(o[j][0] * il0), tf32r(o[j][1] * il0));
        *(float2*)&ap1[j * 8 + 2 * tig] =
            make_float2(tf32r(o[j][2] * il1), tf32r(o[j][3] * il1));
    }
}

// ---------------------------------------------------------------------------
// Launch
// ---------------------------------------------------------------------------
extern "C" void kernel_launch(void* const* d_in, const int* in_sizes, int n_in,
                              void* d_out, int out_size)
{
    const float* x      = (const float*)d_in[0];
    const float* mask   = (const float*)d_in[1];
    const float* w_qkv  = (const float*)d_in[2];
    const float* b_qkv  = (const float*)d_in[3];
    const float* w_proj = (const float*)d_in[4];
    const float* b_proj = (const float*)d_in[5];
    float* out = (float*)d_out;

    float* qkv;   cudaGetSymbolAddress((void**)&qkv,   g_qkv);
    float* att;   cudaGetSymbolAddress((void**)&att,   g_att);
    float* xr;    cudaGetSymbolAddress((void**)&xr,    g_xr);
    float* wqr;   cudaGetSymbolAddress((void**)&wqr,   g_wqkvr);
    float* wpr;   cudaGetSymbolAddress((void**)&wpr,   g_wprojr);

    cudaFuncSetAttribute(gemm_tf32_db_kernel,
                         cudaFuncAttributeMaxDynamicSharedMemorySize, GEMM_SMEM);
    cudaFuncSetAttribute(attn_kernel,
                         cudaFuncAttributeMaxDynamicSharedMemorySize, ATT_SMEM);

    // 0a) mask zero-check (flag consumed by attn_kernel)
    {
        mask_reset_kernel<<<1, 1>>>();
        int n4 = BB * TT * TT / 4;
        mask_check_kernel<<<592, 256>>>((const float4*)mask, n4);
    }

    // 0b) pre-round inputs to tf32
    {
        int n4 = MR * DD / 4;
        round_tf32_kernel<<<(n4 + 255) / 256, 256>>>((const float4*)x, (float4*)xr, n4);
        n4 = QKVN * DD / 4;
        round_tf32_kernel<<<(n4 + 255) / 256, 256>>>((const float4*)w_qkv, (float4*)wqr, n4);
        n4 = DD * DD / 4;
        round_tf32_kernel<<<(n4 + 255) / 256, 256>>>((const float4*)w_proj, (float4*)wpr, n4);
    }

    // 1) QKV projection
    {
        dim3 grid(QKVN / TBN, MR / TBM);
        gemm_tf32_db_kernel<<<grid, 256, GEMM_SMEM>>>(xr, wqr, b_qkv, qkv, QKVN, DD);
    }

    // 2) RoPE + scatter
    {
        int total = BB * TT * HH * 32;
        rope_scatter_kernel<<<(total + 255) / 256, 256>>>();
    }

    // 3) Flash attention
    {
        dim3 grid(TT / QTILE, BB * HH);
        attn_kernel<<<grid, 256, ATT_SMEM>>>(mask);
    }

    // 4) Output projection
    {
        dim3 grid(DD / TBN, MR / TBM);
        gemm_tf32_db_kernel<<<grid, 256, GEMM_SMEM>>>(att, wpr, b_proj, out, DD, DD);
    }
}

// round 12
// speedup vs baseline: 1.0533x; 1.0022x over previous
#include <cuda_runtime.h>
#include <math.h>
#include <stdint.h>

// Problem constants
#define BB   4
#define TT   2048
#define DD   512
#define HH   8
#define DHD  64
#define MR   (BB*TT)       // 8192
#define QKVN (3*DD)        // 1536

// Scratch (device globals -- allocation-free)
__device__ float g_qkv[MR * QKVN];
__device__ float g_q[BB*HH*TT*DHD];       // [b,h,t,d] tf32-rounded
__device__ float g_k[BB*HH*TT*DHD];
__device__ float g_v[BB*HH*TT*DHD];
__device__ float g_att[MR * DD];          // [b*t][D] tf32-rounded
__device__ float g_xr[MR * DD];
__device__ float g_wqkvr[QKVN * DD];
__device__ float g_wprojr[DD * DD];
__device__ int   g_mask_nz;               // 1 if mask has any nonzero

// ---------------------------------------------------------------------------
// helpers
// ---------------------------------------------------------------------------
__device__ __forceinline__ float tf32r(float x)
{
    unsigned u;
    asm("cvt.rna.tf32.f32 %0, %1;" : "=r"(u) : "f"(x));
    return __uint_as_float(u);
}

__device__ __forceinline__ void mma_tf32(float c[4],
                                         unsigned a0, unsigned a1,
                                         unsigned a2, unsigned a3,
                                         unsigned b0, unsigned b1)
{
    asm volatile(
        "mma.sync.aligned.m16n8k8.row.col.f32.tf32.tf32.f32 "
        "{%0,%1,%2,%3}, {%4,%5,%6,%7}, {%8,%9}, {%0,%1,%2,%3};"
        : "+f"(c[0]), "+f"(c[1]), "+f"(c[2]), "+f"(c[3])
        : "r"(a0), "r"(a1), "r"(a2), "r"(a3), "r"(b0), "r"(b1));
}

__device__ __forceinline__ void cp_async16(unsigned dst, const void* src)
{
    asm volatile("cp.async.cg.shared.global [%0], [%1], 16;\n"
                 :: "r"(dst), "l"(src));
}
__device__ __forceinline__ void cp_commit()
{
    asm volatile("cp.async.commit_group;\n");
}
template<int N> __device__ __forceinline__ void cp_wait()
{
    asm volatile("cp.async.wait_group %0;\n" :: "n"(N));
}

__device__ __forceinline__ unsigned smem_u32(const void* p)
{
    return (unsigned)__cvta_generic_to_shared(p);
}

// ---------------------------------------------------------------------------
// pre-round to tf32
// ---------------------------------------------------------------------------
__global__ void round_tf32_kernel(const float4* __restrict__ src,
                                  float4* __restrict__ dst, int n4)
{
    int i = blockIdx.x * blockDim.x + threadIdx.x;
    if (i < n4) {
        float4 v = src[i];
        v.x = tf32r(v.x); v.y = tf32r(v.y);
        v.z = tf32r(v.z); v.w = tf32r(v.w);
        dst[i] = v;
    }
}

// ---------------------------------------------------------------------------
// mask zero-check: g_mask_nz = (any mask element != 0)
// ---------------------------------------------------------------------------
__global__ void mask_reset_kernel() { g_mask_nz = 0; }

__global__ void mask_check_kernel(const float4* __restrict__ m, int n4)
{
    if (g_mask_nz) return;   // someone already found nonzero
    int stride = gridDim.x * blockDim.x;
    int found = 0;
    for (int i = blockIdx.x * blockDim.x + threadIdx.x; i < n4; i += stride) {
        float4 v = m[i];
        if (v.x != 0.0f || v.y != 0.0f || v.z != 0.0f || v.w != 0.0f) {
            found = 1;
            break;
        }
    }
    if (__syncthreads_or(found)) {
        if (threadIdx.x == 0) atomicExch(&g_mask_nz, 1);
    }
}

// ---------------------------------------------------------------------------
// tf32 GEMM, 3-stage cp.async: C = A[M,K] @ Bw[N,K]^T + bias  (R8 version)
// ---------------------------------------------------------------------------
#define TBM 128
#define TBN 128
#define TBK 32
#define TS  36
#define NSTG 3
#define GEMM_SMEM (NSTG * 2 * TBM * TS * 4)

__global__ __launch_bounds__(256, 2)
void gemm_tf32_db_kernel(const float* __restrict__ A,
                         const float* __restrict__ Bw,
                         const float* __restrict__ bias,
                         float* __restrict__ C,
                         int N, int K)
{
    extern __shared__ float gsm[];
    float* As = gsm;
    float* Bs = gsm + NSTG * TBM * TS;

    const int tid  = threadIdx.x;
    const int warp = tid >> 5;
    const int lane = tid & 31;
    const int gid  = lane >> 2;
    const int tig  = lane & 3;
    const int mw   = warp >> 1;
    const int nw   = warp & 1;

    const int mBase = blockIdx.y * TBM;
    const int nBase = blockIdx.x * TBN;

    const unsigned asb = smem_u32(As);
    const unsigned bsb = smem_u32(Bs);

    float acc[2][8][4];
#pragma unroll
    for (int mi = 0; mi < 2; mi++)
#pragma unroll
        for (int j = 0; j < 8; j++)
#pragma unroll
            for (int i = 0; i < 4; i++) acc[mi][j][i] = 0.0f;

    const int niter = K / TBK;
    const int crow = tid >> 3;
    const int cc4  = (tid & 7) << 2;

    auto issue = [&](int kt, int buf) {
        const int k0 = kt * TBK;
        const unsigned abuf = asb + (unsigned)(buf * TBM * TS) * 4u;
        const unsigned bbuf = bsb + (unsigned)(buf * TBN * TS) * 4u;
#pragma unroll
        for (int l = 0; l < 4; l++) {
            int row = crow + l * 32;
            cp_async16(abuf + (unsigned)(row * TS + cc4) * 4u,
                       &A[(size_t)(mBase + row) * K + k0 + cc4]);
        }
#pragma unroll
        for (int l = 0; l < 4; l++) {
            int row = crow + l * 32;
            cp_async16(bbuf + (unsigned)(row * TS + cc4) * 4u,
                       &Bw[(size_t)(nBase + row) * K + k0 + cc4]);
        }
        cp_commit();
    };

    issue(0, 0);
    issue(1, 1);

    for (int i = 0; i < niter; i++) {
        if (i + 1 < niter) cp_wait<1>();
        else               cp_wait<0>();
        __syncthreads();
        if (i + 2 < niter) issue(i + 2, (i + 2) % NSTG);

        const int buf = i % NSTG;
        const float* Ab = As + buf * TBM * TS;
        const float* Bb = Bs + buf * TBN * TS;

#pragma unroll
        for (int kk = 0; kk < TBK; kk += 8) {
            unsigned a[2][4];
#pragma unroll
            for (int mi = 0; mi < 2; mi++) {
                int r0 = (mw * 32 + mi * 16 + gid) * TS;
                a[mi][0] = __float_as_uint(Ab[r0 + kk + tig]);
                a[mi][1] = __float_as_uint(Ab[r0 + 8 * TS + kk + tig]);
                a[mi][2] = __float_as_uint(Ab[r0 + kk + tig + 4]);
                a[mi][3] = __float_as_uint(Ab[r0 + 8 * TS + kk + tig + 4]);
            }
#pragma unroll
            for (int j = 0; j < 8; j++) {
                int rb = (nw * 64 + j * 8 + gid) * TS;
                unsigned b0 = __float_as_uint(Bb[rb + kk + tig]);
                unsigned b1 = __float_as_uint(Bb[rb + kk + tig + 4]);
                mma_tf32(acc[0][j], a[0][0], a[0][1], a[0][2], a[0][3], b0, b1);
                mma_tf32(acc[1][j], a[1][0], a[1][1], a[1][2], a[1][3], b0, b1);
            }
        }
        __syncthreads();
    }

#pragma unroll
    for (int mi = 0; mi < 2; mi++) {
        int m0 = mBase + mw * 32 + mi * 16 + gid;
#pragma unroll
        for (int j = 0; j < 8; j++) {
            int col = nBase + nw * 64 + j * 8 + 2 * tig;
            float2 bv = *(const float2*)&bias[col];
            *(float2*)&C[(size_t)m0 * N + col] =
                make_float2(acc[mi][j][0] + bv.x, acc[mi][j][1] + bv.y);
            *(float2*)&C[(size_t)(m0 + 8) * N + col] =
                make_float2(acc[mi][j][2] + bv.x, acc[mi][j][3] + bv.y);
        }
    }
}

// ---------------------------------------------------------------------------
// RoPE + scatter; outputs tf32-rounded (R8 version)
// ---------------------------------------------------------------------------
__global__ void rope_scatter_kernel()
{
    int idx = blockIdx.x * blockDim.x + threadIdx.x;
    if (idx >= BB * TT * HH * 32) return;
    const int j  = idx & 31;
    const int h  = (idx >> 5) & 7;
    const int bt = idx >> 8;
    const int b  = bt / TT;
    const int t  = bt - b * TT;

    const float* row = g_qkv + (size_t)bt * QKVN;
    const int base = h * DHD;

    float inv = exp2f(-(float)j * 0.41524103736593f);  // log2(10000)/32
    float ang = (float)t * inv;
    float s, c;
    sincosf(ang, &s, &c);

    float q1 = row[base + j],        q2 = row[base + j + 32];
    float k1 = row[DD + base + j],   k2 = row[DD + base + j + 32];
    float v1 = row[2*DD + base + j], v2 = row[2*DD + base + j + 32];

    size_t o = ((size_t)(b * HH + h) * TT + t) * DHD;
    g_q[o + j]      = tf32r(q1 * c - q2 * s);
    g_q[o + j + 32] = tf32r(q2 * c + q1 * s);
    g_k[o + j]      = tf32r(k1 * c - k2 * s);
    g_k[o + j + 32] = tf32r(k2 * c + k1 * s);
    g_v[o + j]      = tf32r(v1);
    g_v[o + j + 32] = tf32r(v2);
}

// ---------------------------------------------------------------------------
// Flash attention v7: R8 tf32 pipeline + zero-mask fast path.
// ---------------------------------------------------------------------------
#define QTILE 128
#define KTILE 64
#define SQ 68
#define SV 72
#define KBUF (KTILE * SQ)
#define VBUF (KTILE * SV)
#define ATT_SMEM ((QTILE*SQ + 2*KBUF + 2*VBUF) * 4)

__device__ __forceinline__ float shfl4(float v, int src)
{
    return __shfl_sync(0xffffffffu, v, src, 4);
}

__global__ __launch_bounds__(256, 2)
void attn_kernel(const float* __restrict__ mask)
{
    extern __shared__ float smf[];
    float* Qs = smf;
    float* Ks = Qs + QTILE * SQ;
    float* Vs = Ks + 2 * KBUF;

    const int bh   = blockIdx.y;
    const int b    = bh >> 3;
    const int h    = bh & 7;
    const int q0   = blockIdx.x * QTILE;
    const int tid  = threadIdx.x;
    const int warp = tid >> 5;
    const int lane = tid & 31;
    const int gid  = lane >> 2;
    const int tig  = lane & 3;
    const int qrow = warp * 16;

    const float scale = 0.125f;
    const bool has_mask = (g_mask_nz != 0);   // uniform branch

    const unsigned ks_u = smem_u32(Ks);
    const unsigned vs_u = smem_u32(Vs);

    const float* kbase = g_k + (size_t)bh * TT * DHD;
    const float* vbase = g_v + (size_t)bh * TT * DHD;

    const int srow = tid >> 2;
    const int sc4  = (tid & 3) << 2;

    auto issue = [&](int kt, int buf) {
        const int k0 = kt * KTILE;
        const unsigned kb = ks_u + (unsigned)(buf * KBUF) * 4u;
        const unsigned vb = vs_u + (unsigned)(buf * VBUF) * 4u;
        const float* kptr = kbase + (size_t)k0 * DHD;
        const float* vptr = vbase + (size_t)k0 * DHD;
#pragma unroll
        for (int l = 0; l < 4; l++) {
            int c4 = sc4 + l * 16;
            cp_async16(kb + (unsigned)(srow * SQ + c4) * 4u,
                       &kptr[srow * DHD + c4]);
            cp_async16(vb + (unsigned)(srow * SV + c4) * 4u,
                       &vptr[srow * DHD + c4]);
        }
        cp_commit();
    };

    const float* qptr = g_q + ((size_t)bh * TT + q0) * DHD;
    for (int l = tid; l < QTILE * 16; l += 256) {
        int r  = l >> 4;
        int c4 = (l & 15) << 2;
        *(float4*)&Qs[r * SQ + c4] = *(const float4*)&qptr[r * DHD + c4];
    }

    issue(0, 0);

    float o[8][4];
#pragma unroll
    for (int j = 0; j < 8; j++)
#pragma unroll
        for (int i = 0; i < 4; i++) o[j][i] = 0.0f;
    float m0 = -1e30f, m1 = -1e30f, l0 = 0.0f, l1 = 0.0f;

    const float* mrow0base = mask + ((size_t)b * TT + q0 + qrow + gid) * TT;

    const int ntiles = TT / KTILE;
    for (int kt = 0; kt < ntiles; kt++) {
        const int k0 = kt * KTILE;

        __syncthreads();
        if (kt + 1 < ntiles) { issue(kt + 1, (kt + 1) & 1); cp_wait<1>(); }
        else                 { cp_wait<0>(); }
        __syncthreads();

        const float* Kb = Ks + (kt & 1) * KBUF;
        const float* Vb = Vs + (kt & 1) * VBUF;

        // mask prefetch only when mask is nonzero
        float2 pm0[8], pm1[8];
        if (has_mask) {
            const float* mr0 = mrow0base + k0;
            const float* mr1 = mr0 + 8 * TT;
#pragma unroll
            for (int j = 0; j < 8; j++) {
                pm0[j] = *(const float2*)&mr0[j * 8 + 2 * tig];
                pm1[j] = *(const float2*)&mr1[j * 8 + 2 * tig];
            }
        }

        // ---- S = Q K^T (tf32) ----
        float c[8][4];
#pragma unroll
        for (int j = 0; j < 8; j++)
#pragma unroll
            for (int i = 0; i < 4; i++) c[j][i] = 0.0f;

#pragma unroll
        for (int d0 = 0; d0 < 64; d0 += 8) {
            unsigned a0 = __float_as_uint(Qs[(qrow + gid) * SQ + d0 + tig]);
            unsigned a1 = __float_as_uint(Qs[(qrow + gid + 8) * SQ + d0 + tig]);
            unsigned a2 = __float_as_uint(Qs[(qrow + gid) * SQ + d0 + tig + 4]);
            unsigned a3 = __float_as_uint(Qs[(qrow + gid + 8) * SQ + d0 + tig + 4]);
#pragma unroll
            for (int j = 0; j < 8; j++) {
                unsigned b0 = __float_as_uint(Kb[(j * 8 + gid) * SQ + d0 + tig]);
                unsigned b1 = __float_as_uint(Kb[(j * 8 + gid) * SQ + d0 + tig + 4]);
                mma_tf32(c[j], a0, a1, a2, a3, b0, b1);
            }
        }

        // ---- scale (+ mask when present) ----
        if (has_mask) {
#pragma unroll
            for (int j = 0; j < 8; j++) {
                c[j][0] = fmaf(c[j][0], scale, pm0[j].x);
                c[j][1] = fmaf(c[j][1], scale, pm0[j].y);
                c[j][2] = fmaf(c[j][2], scale, pm1[j].x);
                c[j][3] = fmaf(c[j][3], scale, pm1[j].y);
            }
        } else {
#pragma unroll
            for (int j = 0; j < 8; j++) {
                c[j][0] *= scale; c[j][1] *= scale;
                c[j][2] *= scale; c[j][3] *= scale;
            }
        }

        // ---- online softmax (quad reduction) ----
        float mt0 = -1e30f, mt1 = -1e30f;
#pragma unroll
        for (int j = 0; j < 8; j++) {
            mt0 = fmaxf(mt0, fmaxf(c[j][0], c[j][1]));
            mt1 = fmaxf(mt1, fmaxf(c[j][2], c[j][3]));
        }
        mt0 = fmaxf(mt0, __shfl_xor_sync(0xffffffffu, mt0, 1));
        mt0 = fmaxf(mt0, __shfl_xor_sync(0xffffffffu, mt0, 2));
        mt1 = fmaxf(mt1, __shfl_xor_sync(0xffffffffu, mt1, 1));
        mt1 = fmaxf(mt1, __shfl_xor_sync(0xffffffffu, mt1, 2));

        float mn0 = fmaxf(m0, mt0);
        float mn1 = fmaxf(m1, mt1);
        float cor0 = __expf(m0 - mn0);
        float cor1 = __expf(m1 - mn1);
        m0 = mn0; m1 = mn1;

        float rs0 = 0.0f, rs1 = 0.0f;
#pragma unroll
        for (int j = 0; j < 8; j++) {
            c[j][0] = __expf(c[j][0] - mn0);
            c[j][1] = __expf(c[j][1] - mn0);
            c[j][2] = __expf(c[j][2] - mn1);
            c[j][3] = __expf(c[j][3] - mn1);
            rs0 += c[j][0] + c[j][1];
            rs1 += c[j][2] + c[j][3];
        }
        rs0 += __shfl_xor_sync(0xffffffffu, rs0, 1);
        rs0 += __shfl_xor_sync(0xffffffffu, rs0, 2);
        rs1 += __shfl_xor_sync(0xffffffffu, rs1, 1);
        rs1 += __shfl_xor_sync(0xffffffffu, rs1, 2);
        l0 = l0 * cor0 + rs0;
        l1 = l1 * cor1 + rs1;

#pragma unroll
        for (int j = 0; j < 8; j++) {
            o[j][0] *= cor0; o[j][1] *= cor0;
            o[j][2] *= cor1; o[j][3] *= cor1;
        }

        // ---- round P; O += P V with C->A frag via quad shuffles ----
#pragma unroll
        for (int j = 0; j < 8; j++) {
            c[j][0] = tf32r(c[j][0]); c[j][1] = tf32r(c[j][1]);
            c[j][2] = tf32r(c[j][2]); c[j][3] = tf32r(c[j][3]);
        }

        const int s0  = tig >> 1;
        const int sel = tig & 1;
#pragma unroll
        for (int mblk = 0; mblk < 8; mblk++) {
            float x00 = shfl4(c[mblk][0], s0);
            float x01 = shfl4(c[mblk][1], s0);
            float x20 = shfl4(c[mblk][2], s0);
            float x21 = shfl4(c[mblk][3], s0);
            float y00 = shfl4(c[mblk][0], s0 + 2);
            float y01 = shfl4(c[mblk][1], s0 + 2);
            float y20 = shfl4(c[mblk][2], s0 + 2);
            float y21 = shfl4(c[mblk][3], s0 + 2);
            unsigned a0 = __float_as_uint(sel ? x01 : x00);
            unsigned a1 = __float_as_uint(sel ? x21 : x20);
            unsigned a2 = __float_as_uint(sel ? y01 : y00);
            unsigned a3 = __float_as_uint(sel ? y21 : y20);
#pragma unroll
            for (int j = 0; j < 8; j++) {
                unsigned b0 = __float_as_uint(Vb[(mblk * 8 + tig) * SV + j * 8 + gid]);
                unsigned b1 = __float_as_uint(Vb[(mblk * 8 + tig + 4) * SV + j * 8 + gid]);
                mma_tf32(o[j], a0, a1, a2, a3, b0, b1);
            }
        }
    }

    float il0 = 1.0f / l0;
    float il1 = 1.0f / l1;
    size_t r0 = (size_t)b * TT + q0 + qrow + gid;
    float* ap0 = g_att + r0 * DD + h * DHD;
    float* ap1 = ap0 + (size_t)8 * DD;
#pragma unroll
    for (int j = 0; j < 8; j++) {
        *(float2*)&ap0[j * 8 + 2 * tig] =
            make_float2(tf32r(o[j][0] * il0), tf32r(o[j][1] * il0));
        *(float2*)&ap1[j * 8 + 2 * tig] =
            make_float2(tf32r(o[j][2] * il1), tf32r(o[j][3] * il1));
    }
}

// ---------------------------------------------------------------------------
// Launch
// ---------------------------------------------------------------------------
extern "C" void kernel_launch(void* const* d_in, const int* in_sizes, int n_in,
                              void* d_out, int out_size)
{
    const float* x      = (const float*)d_in[0];
    const float* mask   = (const float*)d_in[1];
    const float* w_qkv  = (const float*)d_in[2];
    const float* b_qkv  = (const float*)d_in[3];
    const float* w_proj = (const float*)d_in[4];
    const float* b_proj = (const float*)d_in[5];
    float* out = (float*)d_out;

    float* qkv;   cudaGetSymbolAddress((void**)&qkv,   g_qkv);
    float* att;   cudaGetSymbolAddress((void**)&att,   g_att);
    float* xr;    cudaGetSymbolAddress((void**)&xr,    g_xr);
    float* wqr;   cudaGetSymbolAddress((void**)&wqr,   g_wqkvr);
    float* wpr;   cudaGetSymbolAddress((void**)&wpr,   g_wprojr);

    cudaFuncSetAttribute(gemm_tf32_db_kernel,
                         cudaFuncAttributeMaxDynamicSharedMemorySize, GEMM_SMEM);
    cudaFuncSetAttribute(attn_kernel,
                         cudaFuncAttributeMaxDynamicSharedMemorySize, ATT_SMEM);

    // 0a) mask zero-check (flag consumed by attn_kernel)
    {
        mask_reset_kernel<<<1, 1>>>();
        int n4 = BB * TT * TT / 4;
        mask_check_kernel<<<592, 256>>>((const float4*)mask, n4);
    }

    // 0b) pre-round inputs to tf32
    {
        int n4 = MR * DD / 4;
        round_tf32_kernel<<<(n4 + 255) / 256, 256>>>((const float4*)x, (float4*)xr, n4);
        n4 = QKVN * DD / 4;
        round_tf32_kernel<<<(n4 + 255) / 256, 256>>>((const float4*)w_qkv, (float4*)wqr, n4);
        n4 = DD * DD / 4;
        round_tf32_kernel<<<(n4 + 255) / 256, 256>>>((const float4*)w_proj, (float4*)wpr, n4);
    }

    // 1) QKV projection
    {
        dim3 grid(QKVN / TBN, MR / TBM);
        gemm_tf32_db_kernel<<<grid, 256, GEMM_SMEM>>>(xr, wqr, b_qkv, qkv, QKVN, DD);
    }

    // 2) RoPE + scatter
    {
        int total = BB * TT * HH * 32;
        rope_scatter_kernel<<<(total + 255) / 256, 256>>>();
    }

    // 3) Flash attention
    {
        dim3 grid(TT / QTILE, BB * HH);
        attn_kernel<<<grid, 256, ATT_SMEM>>>(mask);
    }

    // 4) Output projection
    {
        dim3 grid(DD / TBN, MR / TBM);
        gemm_tf32_db_kernel<<<grid, 256, GEMM_SMEM>>>(att, wpr, b_proj, out, DD, DD);
    }
}

// round 13
// speedup vs baseline: 1.0538x; 1.0005x over previous
#include <cuda_runtime.h>
#include <math.h>
#include <stdint.h>

// Problem constants
#define BB   4
#define TT   2048
#define DD   512
#define HH   8
#define DHD  64
#define MR   (BB*TT)       // 8192
#define QKVN (3*DD)        // 1536

// Scratch (device globals -- allocation-free)
__device__ float g_qkv[MR * QKVN];
__device__ float g_q[BB*HH*TT*DHD];       // [b,h,t,d] tf32-rounded
__device__ float g_k[BB*HH*TT*DHD];
__device__ float g_v[BB*HH*TT*DHD];
__device__ float g_att[MR * DD];          // [b*t][D] tf32-rounded
__device__ float g_xr[MR * DD];
__device__ float g_wqkvr[QKVN * DD];
__device__ float g_wprojr[DD * DD];
__device__ int   g_mask_nz;               // 1 if mask has any nonzero

// ---------------------------------------------------------------------------
// helpers
// ---------------------------------------------------------------------------
__device__ __forceinline__ float tf32r(float x)
{
    unsigned u;
    asm("cvt.rna.tf32.f32 %0, %1;" : "=r"(u) : "f"(x));
    return __uint_as_float(u);
}

__device__ __forceinline__ void mma_tf32(float c[4],
                                         unsigned a0, unsigned a1,
                                         unsigned a2, unsigned a3,
                                         unsigned b0, unsigned b1)
{
    asm volatile(
        "mma.sync.aligned.m16n8k8.row.col.f32.tf32.tf32.f32 "
        "{%0,%1,%2,%3}, {%4,%5,%6,%7}, {%8,%9}, {%0,%1,%2,%3};"
        : "+f"(c[0]), "+f"(c[1]), "+f"(c[2]), "+f"(c[3])
        : "r"(a0), "r"(a1), "r"(a2), "r"(a3), "r"(b0), "r"(b1));
}

__device__ __forceinline__ void cp_async16(unsigned dst, const void* src)
{
    asm volatile("cp.async.cg.shared.global [%0], [%1], 16;\n"
                 :: "r"(dst), "l"(src));
}
__device__ __forceinline__ void cp_commit()
{
    asm volatile("cp.async.commit_group;\n");
}
template<int N> __device__ __forceinline__ void cp_wait()
{
    asm volatile("cp.async.wait_group %0;\n" :: "n"(N));
}

__device__ __forceinline__ unsigned smem_u32(const void* p)
{
    return (unsigned)__cvta_generic_to_shared(p);
}

// ---------------------------------------------------------------------------
// pre-round to tf32
// ---------------------------------------------------------------------------
__global__ void round_tf32_kernel(const float4* __restrict__ src,
                                  float4* __restrict__ dst, int n4)
{
    int i = blockIdx.x * blockDim.x + threadIdx.x;
    if (i < n4) {
        float4 v = src[i];
        v.x = tf32r(v.x); v.y = tf32r(v.y);
        v.z = tf32r(v.z); v.w = tf32r(v.w);
        dst[i] = v;
    }
}

// ---------------------------------------------------------------------------
// mask zero-check: g_mask_nz = (any mask element != 0)
// ---------------------------------------------------------------------------
__global__ void mask_reset_kernel() { g_mask_nz = 0; }

__global__ void mask_check_kernel(const float4* __restrict__ m, int n4)
{
    if (g_mask_nz) return;   // someone already found nonzero
    int stride = gridDim.x * blockDim.x;
    int found = 0;
    for (int i = blockIdx.x * blockDim.x + threadIdx.x; i < n4; i += stride) {
        float4 v = m[i];
        if (v.x != 0.0f || v.y != 0.0f || v.z != 0.0f || v.w != 0.0f) {
            found = 1;
            break;
        }
    }
    if (__syncthreads_or(found)) {
        if (threadIdx.x == 0) atomicExch(&g_mask_nz, 1);
    }
}

// ---------------------------------------------------------------------------
// tf32 GEMM, 3-stage cp.async: C = A[M,K] @ Bw[N,K]^T + bias  (R8 version)
// ---------------------------------------------------------------------------
#define TBM 128
#define TBN 128
#define TBK 32
#define TS  36
#define NSTG 3
#define GEMM_SMEM (NSTG * 2 * TBM * TS * 4)

__global__ __launch_bounds__(256, 2)
void gemm_tf32_db_kernel(const float* __restrict__ A,
                         const float* __restrict__ Bw,
                         const float* __restrict__ bias,
                         float* __restrict__ C,
                         int N, int K)
{
    extern __shared__ float gsm[];
    float* As = gsm;
    float* Bs = gsm + NSTG * TBM * TS;

    const int tid  = threadIdx.x;
    const int warp = tid >> 5;
    const int lane = tid & 31;
    const int gid  = lane >> 2;
    const int tig  = lane & 3;
    const int mw   = warp >> 1;
    const int nw   = warp & 1;

    const int mBase = blockIdx.y * TBM;
    const int nBase = blockIdx.x * TBN;

    const unsigned asb = smem_u32(As);
    const unsigned bsb = smem_u32(Bs);

    float acc[2][8][4];
#pragma unroll
    for (int mi = 0; mi < 2; mi++)
#pragma unroll
        for (int j = 0; j < 8; j++)
#pragma unroll
            for (int i = 0; i < 4; i++) acc[mi][j][i] = 0.0f;

    const int niter = K / TBK;
    const int crow = tid >> 3;
    const int cc4  = (tid & 7) << 2;

    auto issue = [&](int kt, int buf) {
        const int k0 = kt * TBK;
        const unsigned abuf = asb + (unsigned)(buf * TBM * TS) * 4u;
        const unsigned bbuf = bsb + (unsigned)(buf * TBN * TS) * 4u;
#pragma unroll
        for (int l = 0; l < 4; l++) {
            int row = crow + l * 32;
            cp_async16(abuf + (unsigned)(row * TS + cc4) * 4u,
                       &A[(size_t)(mBase + row) * K + k0 + cc4]);
        }
#pragma unroll
        for (int l = 0; l < 4; l++) {
            int row = crow + l * 32;
            cp_async16(bbuf + (unsigned)(row * TS + cc4) * 4u,
                       &Bw[(size_t)(nBase + row) * K + k0 + cc4]);
        }
        cp_commit();
    };

    issue(0, 0);
    issue(1, 1);

    for (int i = 0; i < niter; i++) {
        if (i + 1 < niter) cp_wait<1>();
        else               cp_wait<0>();
        __syncthreads();
        if (i + 2 < niter) issue(i + 2, (i + 2) % NSTG);

        const int buf = i % NSTG;
        const float* Ab = As + buf * TBM * TS;
        const float* Bb = Bs + buf * TBN * TS;

#pragma unroll
        for (int kk = 0; kk < TBK; kk += 8) {
            unsigned a[2][4];
#pragma unroll
            for (int mi = 0; mi < 2; mi++) {
                int r0 = (mw * 32 + mi * 16 + gid) * TS;
                a[mi][0] = __float_as_uint(Ab[r0 + kk + tig]);
                a[mi][1] = __float_as_uint(Ab[r0 + 8 * TS + kk + tig]);
                a[mi][2] = __float_as_uint(Ab[r0 + kk + tig + 4]);
                a[mi][3] = __float_as_uint(Ab[r0 + 8 * TS + kk + tig + 4]);
            }
#pragma unroll
            for (int j = 0; j < 8; j++) {
                int rb = (nw * 64 + j * 8 + gid) * TS;
                unsigned b0 = __float_as_uint(Bb[rb + kk + tig]);
                unsigned b1 = __float_as_uint(Bb[rb + kk + tig + 4]);
                mma_tf32(acc[0][j], a[0][0], a[0][1], a[0][2], a[0][3], b0, b1);
                mma_tf32(acc[1][j], a[1][0], a[1][1], a[1][2], a[1][3], b0, b1);
            }
        }
        __syncthreads();
    }

#pragma unroll
    for (int mi = 0; mi < 2; mi++) {
        int m0 = mBase + mw * 32 + mi * 16 + gid;
#pragma unroll
        for (int j = 0; j < 8; j++) {
            int col = nBase + nw * 64 + j * 8 + 2 * tig;
            float2 bv = *(const float2*)&bias[col];
            *(float2*)&C[(size_t)m0 * N + col] =
                make_float2(acc[mi][j][0] + bv.x, acc[mi][j][1] + bv.y);
            *(float2*)&C[(size_t)(m0 + 8) * N + col] =
                make_float2(acc[mi][j][2] + bv.x, acc[mi][j][3] + bv.y);
        }
    }
}

// ---------------------------------------------------------------------------
// RoPE + scatter; outputs tf32-rounded (R8 version)
// ---------------------------------------------------------------------------
__global__ void rope_scatter_kernel()
{
    int idx = blockIdx.x * blockDim.x + threadIdx.x;
    if (idx >= BB * TT * HH * 32) return;
    const int j  = idx & 31;
    const int h  = (idx >> 5) & 7;
    const int bt = idx >> 8;
    const int b  = bt / TT;
    const int t  = bt - b * TT;

    const float* row = g_qkv + (size_t)bt * QKVN;
    const int base = h * DHD;

    float inv = exp2f(-(float)j * 0.41524103736593f);  // log2(10000)/32
    float ang = (float)t * inv;
    float s, c;
    sincosf(ang, &s, &c);

    float q1 = row[base + j],        q2 = row[base + j + 32];
    float k1 = row[DD + base + j],   k2 = row[DD + base + j + 32];
    float v1 = row[2*DD + base + j], v2 = row[2*DD + base + j + 32];

    size_t o = ((size_t)(b * HH + h) * TT + t) * DHD;
    g_q[o + j]      = tf32r(q1 * c - q2 * s);
    g_q[o + j + 32] = tf32r(q2 * c + q1 * s);
    g_k[o + j]      = tf32r(k1 * c - k2 * s);
    g_k[o + j + 32] = tf32r(k2 * c + k1 * s);
    g_v[o + j]      = tf32r(v1);
    g_v[o + j + 32] = tf32r(v2);
}

// ---------------------------------------------------------------------------
// Flash attention v7: R8 tf32 pipeline + zero-mask fast path.
// ---------------------------------------------------------------------------
#define QTILE 128
#define KTILE 64
#define SQ 68
#define SV 72
#define KBUF (KTILE * SQ)
#define VBUF (KTILE * SV)
#define ATT_SMEM ((QTILE*SQ + 2*KBUF + 2*VBUF) * 4)

__device__ __forceinline__ float shfl4(float v, int src)
{
    return __shfl_sync(0xffffffffu, v, src, 4);
}

__global__ __launch_bounds__(256, 2)
void attn_kernel(const float* __restrict__ mask)
{
    extern __shared__ float smf[];
    float* Qs = smf;
    float* Ks = Qs + QTILE * SQ;
    float* Vs = Ks + 2 * KBUF;

    const int bh   = blockIdx.y;
    const int b    = bh >> 3;
    const int h    = bh & 7;
    const int q0   = blockIdx.x * QTILE;
    const int tid  = threadIdx.x;
    const int warp = tid >> 5;
    const int lane = tid & 31;
    const int gid  = lane >> 2;
    const int tig  = lane & 3;
    const int qrow = warp * 16;

    const float scale = 0.125f;
    const bool has_mask = (g_mask_nz != 0);   // uniform branch

    const unsigned ks_u = smem_u32(Ks);
    const unsigned vs_u = smem_u32(Vs);

    const float* kbase = g_k + (size_t)bh * TT * DHD;
    const float* vbase = g_v + (size_t)bh * TT * DHD;

    const int srow = tid >> 2;
    const int sc4  = (tid & 3) << 2;

    auto issue = [&](int kt, int buf) {
        const int k0 = kt * KTILE;
        const unsigned kb = ks_u + (unsigned)(buf * KBUF) * 4u;
        const unsigned vb = vs_u + (unsigned)(buf * VBUF) * 4u;
        const float* kptr = kbase + (size_t)k0 * DHD;
        const float* vptr = vbase + (size_t)k0 * DHD;
#pragma unroll
        for (int l = 0; l < 4; l++) {
            int c4 = sc4 + l * 16;
            cp_async16(kb + (unsigned)(srow * SQ + c4) * 4u,
                       &kptr[srow * DHD + c4]);
            cp_async16(vb + (unsigned)(srow * SV + c4) * 4u,
                       &vptr[srow * DHD + c4]);
        }
        cp_commit();
    };

    const float* qptr = g_q + ((size_t)bh * TT + q0) * DHD;
    for (int l = tid; l < QTILE * 16; l += 256) {
        int r  = l >> 4;
        int c4 = (l & 15) << 2;
        *(float4*)&Qs[r * SQ + c4] = *(const float4*)&qptr[r * DHD + c4];
    }

    issue(0, 0);

    float o[8][4];
#pragma unroll
    for (int j = 0; j < 8; j++)
#pragma unroll
        for (int i = 0; i < 4; i++) o[j][i] = 0.0f;
    float m0 = -1e30f, m1 = -1e30f, l0 = 0.0f, l1 = 0.0f;

    const float* mrow0base = mask + ((size_t)b * TT + q0 + qrow + gid) * TT;

    const int ntiles = TT / KTILE;
    for (int kt = 0; kt < ntiles; kt++) {
        const int k0 = kt * KTILE;

        __syncthreads();
        if (kt + 1 < ntiles) { issue(kt + 1, (kt + 1) & 1); cp_wait<1>(); }
        else                 { cp_wait<0>(); }
        __syncthreads();

        const float* Kb = Ks + (kt & 1) * KBUF;
        const float* Vb = Vs + (kt & 1) * VBUF;

        // mask prefetch only when mask is nonzero
        float2 pm0[8], pm1[8];
        if (has_mask) {
            const float* mr0 = mrow0base + k0;
            const float* mr1 = mr0 + 8 * TT;
#pragma unroll
            for (int j = 0; j < 8; j++) {
                pm0[j] = *(const float2*)&mr0[j * 8 + 2 * tig];
                pm1[j] = *(const float2*)&mr1[j * 8 + 2 * tig];
            }
        }

        // ---- S = Q K^T (tf32) ----
        float c[8][4];
#pragma unroll
        for (int j = 0; j < 8; j++)
#pragma unroll
            for (int i = 0; i < 4; i++) c[j][i] = 0.0f;

#pragma unroll
        for (int d0 = 0; d0 < 64; d0 += 8) {
            unsigned a0 = __float_as_uint(Qs[(qrow + gid) * SQ + d0 + tig]);
            unsigned a1 = __float_as_uint(Qs[(qrow + gid + 8) * SQ + d0 + tig]);
            unsigned a2 = __float_as_uint(Qs[(qrow + gid) * SQ + d0 + tig + 4]);
            unsigned a3 = __float_as_uint(Qs[(qrow + gid + 8) * SQ + d0 + tig + 4]);
#pragma unroll
            for (int j = 0; j < 8; j++) {
                unsigned b0 = __float_as_uint(Kb[(j * 8 + gid) * SQ + d0 + tig]);
                unsigned b1 = __float_as_uint(Kb[(j * 8 + gid) * SQ + d0 + tig + 4]);
                mma_tf32(c[j], a0, a1, a2, a3, b0, b1);
            }
        }

        // ---- scale (+ mask when present) ----
        if (has_mask) {
#pragma unroll
            for (int j = 0; j < 8; j++) {
                c[j][0] = fmaf(c[j][0], scale, pm0[j].x);
                c[j][1] = fmaf(c[j][1], scale, pm0[j].y);
                c[j][2] = fmaf(c[j][2], scale, pm1[j].x);
                c[j][3] = fmaf(c[j][3], scale, pm1[j].y);
            }
        } else {
#pragma unroll
            for (int j = 0; j < 8; j++) {
                c[j][0] *= scale; c[j][1] *= scale;
                c[j][2] *= scale; c[j][3] *= scale;
            }
        }

        // ---- online softmax (quad reduction) ----
        float mt0 = -1e30f, mt1 = -1e30f;
#pragma unroll
        for (int j = 0; j < 8; j++) {
            mt0 = fmaxf(mt0, fmaxf(c[j][0], c[j][1]));
            mt1 = fmaxf(mt1, fmaxf(c[j][2], c[j][3]));
        }
        mt0 = fmaxf(mt0, __shfl_xor_sync(0xffffffffu, mt0, 1));
        mt0 = fmaxf(mt0, __shfl_xor_sync(0xffffffffu, mt0, 2));
        mt1 = fmaxf(mt1, __shfl_xor_sync(0xffffffffu, mt1, 1));
        mt1 = fmaxf(mt1, __shfl_xor_sync(0xffffffffu, mt1, 2));

        float mn0 = fmaxf(m0, mt0);
        float mn1 = fmaxf(m1, mt1);
        float cor0 = __expf(m0 - mn0);
        float cor1 = __expf(m1 - mn1);
        m0 = mn0; m1 = mn1;

        float rs0 = 0.0f, rs1 = 0.0f;
#pragma unroll
        for (int j = 0; j < 8; j++) {
            c[j][0] = __expf(c[j][0] - mn0);
            c[j][1] = __expf(c[j][1] - mn0);
            c[j][2] = __expf(c[j][2] - mn1);
            c[j][3] = __expf(c[j][3] - mn1);
            rs0 += c[j][0] + c[j][1];
            rs1 += c[j][2] + c[j][3];
        }
        rs0 += __shfl_xor_sync(0xffffffffu, rs0, 1);
        rs0 += __shfl_xor_sync(0xffffffffu, rs0, 2);
        rs1 += __shfl_xor_sync(0xffffffffu, rs1, 1);
        rs1 += __shfl_xor_sync(0xffffffffu, rs1, 2);
        l0 = l0 * cor0 + rs0;
        l1 = l1 * cor1 + rs1;

#pragma unroll
        for (int j = 0; j < 8; j++) {
            o[j][0] *= cor0; o[j][1] *= cor0;
            o[j][2] *= cor1; o[j][3] *= cor1;
        }

        // ---- round P; O += P V with C->A frag via quad shuffles ----
#pragma unroll
        for (int j = 0; j < 8; j++) {
            c[j][0] = tf32r(c[j][0]); c[j][1] = tf32r(c[j][1]);
            c[j][2] = tf32r(c[j][2]); c[j][3] = tf32r(c[j][3]);
        }

        const int s0  = tig >> 1;
        const int sel = tig & 1;
#pragma unroll
        for (int mblk = 0; mblk < 8; mblk++) {
            float x00 = shfl4(c[mblk][0], s0);
            float x01 = shfl4(c[mblk][1], s0);
            float x20 = shfl4(c[mblk][2], s0);
            float x21 = shfl4(c[mblk][3], s0);
            float y00 = shfl4(c[mblk][0], s0 + 2);
            float y01 = shfl4(c[mblk][1], s0 + 2);
            float y20 = shfl4(c[mblk][2], s0 + 2);
            float y21 = shfl4(c[mblk][3], s0 + 2);
            unsigned a0 = __float_as_uint(sel ? x01 : x00);
            unsigned a1 = __float_as_uint(sel ? x21 : x20);
            unsigned a2 = __float_as_uint(sel ? y01 : y00);
            unsigned a3 = __float_as_uint(sel ? y21 : y20);
#pragma unroll
            for (int j = 0; j < 8; j++) {
                unsigned b0 = __float_as_uint(Vb[(mblk * 8 + tig) * SV + j * 8 + gid]);
                unsigned b1 = __float_as_uint(Vb[(mblk * 8 + tig + 4) * SV + j * 8 + gid]);
                mma_tf32(o[j], a0, a1, a2, a3, b0, b1);
            }
        }
    }

    float il0 = 1.0f / l0;
    float il1 = 1.0f / l1;
    size_t r0 = (size_t)b * TT + q0 + qrow + gid;
    float* ap0 = g_att + r0 * DD + h * DHD;
    float* ap1 = ap0 + (size_t)8 * DD;
#pragma unroll
    for (int j = 0; j < 8; j++) {
        *(float2*)&ap0[j * 8 + 2 * tig] =
            make_float2(tf32r(o[j][0] * il0), tf32r(o[j][1] * il0));
        *(float2*)&ap1[j * 8 + 2 * tig] =
            make_float2(tf32r(o[j][2] * il1), tf32r(o[j][3] * il1));
    }
}

// ---------------------------------------------------------------------------
// Launch
// ---------------------------------------------------------------------------
extern "C" void kernel_launch(void* const* d_in, const int* in_sizes, int n_in,
                              void* d_out, int out_size)
{
    const float* x      = (const float*)d_in[0];
    const float* mask   = (const float*)d_in[1];
    const float* w_qkv  = (const float*)d_in[2];
    const float* b_qkv  = (const float*)d_in[3];
    const float* w_proj = (const float*)d_in[4];
    const float* b_proj = (const float*)d_in[5];
    float* out = (float*)d_out;

    float* qkv;   cudaGetSymbolAddress((void**)&qkv,   g_qkv);
    float* att;   cudaGetSymbolAddress((void**)&att,   g_att);
    float* xr;    cudaGetSymbolAddress((void**)&xr,    g_xr);
    float* wqr;   cudaGetSymbolAddress((void**)&wqr,   g_wqkvr);
    float* wpr;   cudaGetSymbolAddress((void**)&wpr,   g_wprojr);

    cudaFuncSetAttribute(gemm_tf32_db_kernel,
                         cudaFuncAttributeMaxDynamicSharedMemorySize, GEMM_SMEM);
    cudaFuncSetAttribute(attn_kernel,
                         cudaFuncAttributeMaxDynamicSharedMemorySize, ATT_SMEM);

    // 0a) mask zero-check (flag consumed by attn_kernel)
    {
        mask_reset_kernel<<<1, 1>>>();
        int n4 = BB * TT * TT / 4;
        mask_check_kernel<<<592, 256>>>((const float4*)mask, n4);
    }

    // 0b) pre-round inputs to tf32
    {
        int n4 = MR * DD / 4;
        round_tf32_kernel<<<(n4 + 255) / 256, 256>>>((const float4*)x, (float4*)xr, n4);
        n4 = QKVN * DD / 4;
        round_tf32_kernel<<<(n4 + 255) / 256, 256>>>((const float4*)w_qkv, (float4*)wqr, n4);
        n4 = DD * DD / 4;
        round_tf32_kernel<<<(n4 + 255) / 256, 256>>>((const float4*)w_proj, (float4*)wpr, n4);
    }

    // 1) QKV projection
    {
        dim3 grid(QKVN / TBN, MR / TBM);
        gemm_tf32_db_kernel<<<grid, 256, GEMM_SMEM>>>(xr, wqr, b_qkv, qkv, QKVN, DD);
    }

    // 2) RoPE + scatter
    {
        int total = BB * TT * HH * 32;
        rope_scatter_kernel<<<(total + 255) / 256, 256>>>();
    }

    // 3) Flash attention
    {
        dim3 grid(TT / QTILE, BB * HH);
        attn_kernel<<<grid, 256, ATT_SMEM>>>(mask);
    }

    // 4) Output projection
    {
        dim3 grid(DD / TBN, MR / TBM);
        gemm_tf32_db_kernel<<<grid, 256, GEMM_SMEM>>>(att, wpr, b_proj, out, DD, DD);
    }
}